// round 17
// baseline (speedup 1.0000x reference)
#include <cuda_runtime.h>
#include <cstdint>

#define BATCH 16
#define NA    25200
#define NC    80
#define TOPK  2048
#define NMS_T 0.45f
#define CONF_T 0.25f
#define FULLM 0xffffffffu

// ---------------- scratch (__device__ globals; zero-initialized at load) ----------------
__device__ float              g_scores[BATCH * NA];          // conf-filtered max score
__device__ int                g_labels[BATCH * NA];          // argmax class
__device__ float              g_topboxes[BATCH * TOPK * 4];  // gathered boxes (xyxy)
__device__ float              g_topscore[BATCH * TOPK];
__device__ int                g_topidx[BATCH * TOPK];
__device__ __align__(16) unsigned long long g_mask[(size_t)BATCH * TOPK * 32]; // 8MB bit-matrix

// ---------------- K1: score/argmax, smem-staged coalesced loads ----------------
__global__ void __launch_bounds__(128) k_scores(const float* __restrict__ obj,
                                                const float* __restrict__ cls) {
    __shared__ float sh[128 * 81];                 // 81-stride: conflict-free reduce
    const int t = threadIdx.x;
    const int a0 = blockIdx.x * 128;               // first flattened anchor of block
    const float4* __restrict__ src = reinterpret_cast<const float4*>(cls) + (size_t)a0 * 20;

#pragma unroll
    for (int k = 0; k < 20; ++k) {                 // perfectly coalesced gmem loads
        int fi = k * 128 + t;
        float4 v = src[fi];
        int a = fi / 20, c = (fi % 20) * 4;
        float* row = sh + a * 81 + c;
        row[0] = v.x; row[1] = v.y; row[2] = v.z; row[3] = v.w;
    }
    __syncthreads();

    const int g = a0 + t;
    const float o = obj[g];
    const float* row = sh + t * 81;
    float best = -1.0f; int bi = 0;
#pragma unroll
    for (int c = 0; c < NC; ++c) {                 // strict > : first-index argmax
        float p = o * row[c];
        if (p > best) { best = p; bi = c; }
    }
    g_scores[g] = (best > CONF_T) ? best : 0.0f;
    g_labels[g] = bi;
}

// ---------------- K2: per-image exact top-2048 (sorted desc, tie -> low idx) ----------------
// composite key: (float_bits(score) << 15) | (32767 - idx)   -- 48 bits, all distinct
// 4-pass 12-bit radix select with warp-parallel 3-level digit search. (R14/R16 proven)
__global__ void k_topk(const float* __restrict__ boxes) {
    const int b = blockIdx.x;
    const int t = threadIdx.x;                 // 1024 threads
    const float* __restrict__ sc = g_scores + (size_t)b * NA;

    __shared__ unsigned int hist[4096];
    __shared__ unsigned long long keys[TOPK];
    __shared__ unsigned long long sh_prefix;
    __shared__ int sh_rem;
    __shared__ unsigned int sh_cnt;

    if (t == 0) { sh_prefix = 0ull; sh_rem = TOPK; sh_cnt = 0u; }
    for (int i = t; i < TOPK; i += 1024) keys[i] = 0ull;
    __syncthreads();

    for (int shift = 36; shift >= 0; shift -= 12) {
        for (int i = t; i < 4096; i += 1024) hist[i] = 0u;
        __syncthreads();
        unsigned long long prefix = sh_prefix;
        for (int n = t; n < NA; n += 1024) {
            unsigned long long key =
                ((unsigned long long)__float_as_uint(sc[n]) << 15) |
                (unsigned long long)(32767 - n);
            if ((key >> (shift + 12)) == prefix)
                atomicAdd(&hist[(unsigned)(key >> shift) & 4095u], 1u);
        }
        __syncthreads();
        if (t < 32) {                              // warp 0: parallel digit search
            const int lane = t;
            unsigned rem = (unsigned)sh_rem;
            unsigned a0 = 0, a1 = 0, a2 = 0, a3 = 0;
            int base1 = lane * 128;
            for (int i = 0; i < 128; i += 4) {
                a0 += hist[base1 + i + 0]; a1 += hist[base1 + i + 1];
                a2 += hist[base1 + i + 2]; a3 += hist[base1 + i + 3];
            }
            unsigned c1 = a0 + a1 + a2 + a3;
            unsigned v = c1;                       // inclusive suffix sum over lanes
            for (int o = 1; o < 32; o <<= 1) {
                unsigned u = __shfl_down_sync(FULLM, v, o);
                if (lane + o < 32) v += u;
            }
            unsigned sufex = v - c1;
            unsigned bal = __ballot_sync(FULLM, (sufex < rem) && (rem <= v));
            int L1 = __ffs(bal) - 1;
            rem -= __shfl_sync(FULLM, sufex, L1);
            int base2 = L1 * 128 + lane * 4;
            unsigned c2 = hist[base2] + hist[base2 + 1] + hist[base2 + 2] + hist[base2 + 3];
            v = c2;
            for (int o = 1; o < 32; o <<= 1) {
                unsigned u = __shfl_down_sync(FULLM, v, o);
                if (lane + o < 32) v += u;
            }
            sufex = v - c2;
            bal = __ballot_sync(FULLM, (sufex < rem) && (rem <= v));
            int L2 = __ffs(bal) - 1;
            rem -= __shfl_sync(FULLM, sufex, L2);
            if (lane == L2) {
                int b3 = L1 * 128 + L2 * 4;
                unsigned cum = 0; int d = 3;
                for (d = 3; d >= 0; --d) {
                    unsigned h = hist[b3 + d];
                    if (cum + h >= rem) break;
                    cum += h;
                }
                sh_prefix = (prefix << 12) | (unsigned long long)(unsigned)(b3 + d);
                sh_rem = (int)(rem - cum);
            }
        }
        __syncthreads();
    }
    const unsigned long long T = sh_prefix;    // exact K-th largest key

    for (int n = t; n < NA; n += 1024) {
        unsigned long long key =
            ((unsigned long long)__float_as_uint(sc[n]) << 15) |
            (unsigned long long)(32767 - n);
        if (key >= T) {
            unsigned p = atomicAdd(&sh_cnt, 1u);
            if (p < TOPK) keys[p] = key;
        }
    }
    __syncthreads();

    // bitonic sort descending (2048 elems, 1024 threads)
    for (int kk = 2; kk <= TOPK; kk <<= 1) {
        for (int j = kk >> 1; j > 0; j >>= 1) {
            for (int i = t; i < TOPK; i += 1024) {
                int l = i ^ j;
                if (l > i) {
                    bool dir = ((i & kk) == 0);  // true -> descending
                    unsigned long long a = keys[i], c = keys[l];
                    if ((a < c) == dir) { keys[i] = c; keys[l] = a; }
                }
            }
            __syncthreads();
        }
    }

    for (int r = t; r < TOPK; r += 1024) {
        unsigned long long key = keys[r];
        int idx = 32767 - (int)(key & 0x7FFFull);
        float score = __uint_as_float((unsigned)(key >> 15));
        int o = b * TOPK + r;
        g_topidx[o] = idx;
        g_topscore[o] = score;
        float4 bx = reinterpret_cast<const float4*>(boxes)[(size_t)b * NA + idx];
        reinterpret_cast<float4*>(g_topboxes)[o] = bx;
    }
}

// ---------------- K3: 64x64 suppression bit-tiles (upper triangle only) ----------------
__device__ __forceinline__ bool iou_sup(const float4& rb, float area1,
                                        const float4& c, float area2) {
    float lx = fmaxf(rb.x, c.x), ly = fmaxf(rb.y, c.y);
    float rx = fminf(rb.z, c.z), ry = fminf(rb.w, c.w);
    float w = fmaxf(rx - lx, 0.0f), h = fmaxf(ry - ly, 0.0f);
    float inter = w * h;
    if (inter > 0.0f) {
        float un = area1 + area2 - inter;
        return __fdiv_rn(inter, un) > NMS_T;   // IEEE div: matches XLA div.rn
    }
    return false;
}

__global__ void k_mask() {
    if (blockIdx.x < blockIdx.y) return;   // strictly-lower tiles stay zero (never written)
    const int b = blockIdx.z;
    const int rowblk = blockIdx.y, colblk = blockIdx.x;
    const int t = threadIdx.x;             // 64 threads
    __shared__ float4 colbox[64];
    __shared__ float colarea[64];

    const int col0 = colblk * 64;
    float4 cbl = reinterpret_cast<const float4*>(g_topboxes)[b * TOPK + col0 + t];
    colbox[t] = cbl;
    colarea[t] = (cbl.z - cbl.x) * (cbl.w - cbl.y);
    __syncthreads();

    const int row = rowblk * 64 + t;
    float4 rb = reinterpret_cast<const float4*>(g_topboxes)[b * TOPK + row];
    float area1 = (rb.z - rb.x) * (rb.w - rb.y);

    unsigned long long bits = 0ull;
    if (rowblk != colblk) {
#pragma unroll 4
        for (int j = 0; j < 64; ++j)
            if (iou_sup(rb, area1, colbox[j], colarea[j])) bits |= (1ull << j);
    } else {
#pragma unroll 4
        for (int j = 0; j < 64; ++j)
            if (col0 + j > row && iou_sup(rb, area1, colbox[j], colarea[j]))
                bits |= (1ull << j);
    }
    g_mask[((size_t)b * TOPK + row) * 32 + colblk] = bits;
}

// ---------------- K4: greedy reduce w/ bulk-async ring + overlapped finalize ----------------
#define RING_N 6

__device__ __forceinline__ void mbar_init(unsigned a, unsigned cnt) {
    asm volatile("mbarrier.init.shared.b64 [%0], %1;" :: "r"(a), "r"(cnt) : "memory");
}
__device__ __forceinline__ void bulk_issue(unsigned mbar, unsigned dst,
                                           const void* src, unsigned bytes) {
    asm volatile("mbarrier.arrive.expect_tx.shared.b64 _, [%0], %1;"
                 :: "r"(mbar), "r"(bytes) : "memory");
    asm volatile("cp.async.bulk.shared::cta.global.mbarrier::complete_tx::bytes "
                 "[%0], [%1], %2, [%3];"
                 :: "r"(dst), "l"(src), "r"(bytes), "r"(mbar) : "memory");
}
__device__ __forceinline__ void mbar_wait(unsigned a, unsigned phase) {
    unsigned done;
    asm volatile(
        "{\n\t.reg .pred p;\n\t"
        "mbarrier.try_wait.parity.acquire.cta.shared::cta.b64 p, [%1], %2;\n\t"
        "selp.b32 %0, 1, 0, p;\n\t}"
        : "=r"(done) : "r"(a), "r"(phase) : "memory");
    while (!done) {
        asm volatile(
            "{\n\t.reg .pred p;\n\t"
            "mbarrier.try_wait.parity.acquire.cta.shared::cta.b64 p, [%1], %2, 0x989680;\n\t"
            "selp.b32 %0, 1, 0, p;\n\t}"
            : "=r"(done) : "r"(a), "r"(phase) : "memory");
    }
}

__global__ void __launch_bounds__(1024, 1) k_reduce_final(float* __restrict__ out) {
    __shared__ __align__(128) unsigned long long ring[RING_N][1024];  // 48 KB
    __shared__ __align__(8)   unsigned long long mbar[RING_N];
    __shared__ unsigned char keepsh[TOPK];
    const int b = blockIdx.x;
    const int t = threadIdx.x;

    // ---- all warps: preload finalize data (label gather hides under the chain) ----
    const int r0 = t, r1 = t + 1024;
    const int g0 = b * TOPK + r0, g1 = b * TOPK + r1;
    float4 bx0 = reinterpret_cast<const float4*>(g_topboxes)[g0];
    float4 bx1 = reinterpret_cast<const float4*>(g_topboxes)[g1];
    float s0 = g_topscore[g0], s1 = g_topscore[g1];
    float lab0 = (float)g_labels[(size_t)b * NA + g_topidx[g0]];
    float lab1 = (float)g_labels[(size_t)b * NA + g_topidx[g1]];

    if (t < 32) {
        const int lane = t;                    // lane owns column word lane (cols lane*64..+63)
        const unsigned long long* __restrict__ M = g_mask + (size_t)b * TOPK * 32;
        const unsigned mb0 = (unsigned)__cvta_generic_to_shared(&mbar[0]);
        const unsigned rg0 = (unsigned)__cvta_generic_to_shared(&ring[0][0]);

        if (lane == 0) {
#pragma unroll
            for (int s = 0; s < RING_N; ++s) mbar_init(mb0 + s * 8, 1);
        }
        __syncwarp();
        if (lane == 0) {
#pragma unroll
            for (int c = 0; c < RING_N - 1; ++c)   // 5 chunks in flight
                bulk_issue(mb0 + (c % RING_N) * 8, rg0 + (c % RING_N) * 8192,
                           M + (size_t)c * 1024, 8192);
        }
        __syncwarp();

        unsigned long long keep0w = 0ull;
        const float* ts = g_topscore + b * TOPK;
#pragma unroll 8
        for (int q = 0; q < 64; ++q)
            if (ts[lane * 64 + q] > 0.0f) keep0w |= (1ull << q);

        unsigned long long removed = 0ull;

        for (int c = 0; c < 64; ++c) {
            const int slot = c % RING_N;
            mbar_wait(mb0 + slot * 8, (unsigned)((c / RING_N) & 1));

            const unsigned long long* rowp = ring[slot];
            const int owner = c >> 1;
            const int sh2 = (c & 1) * 32;

            unsigned d[32];
#pragma unroll
            for (int i = 0; i < 32; ++i)
                d[i] = (unsigned)(rowp[i * 32 + owner] >> sh2);

            unsigned long long av64 = __shfl_sync(FULLM, keep0w & ~removed, owner);
            unsigned alive = (unsigned)(av64 >> sh2);

#pragma unroll
            for (int i = 0; i < 32; ++i)
                alive &= ~(d[i] & (unsigned)((int)(alive << (31 - i)) >> 31));

            // branchless OR of alive rows into this lane's removed word
#pragma unroll
            for (int i = 0; i < 32; ++i) {
                unsigned long long m =
                    (unsigned long long)(long long)((int)(alive << (31 - i)) >> 31);
                removed |= rowp[i * 32 + lane] & m;
            }

            keepsh[c * 32 + lane] = (unsigned char)((alive >> lane) & 1u);

            if (lane == 0 && c + RING_N - 1 < 64) {
                int nc = c + RING_N - 1;
                bulk_issue(mb0 + (nc % RING_N) * 8, rg0 + (nc % RING_N) * 8192,
                           M + (size_t)nc * 1024, 8192);
            }
        }
    }
    __syncthreads();

    // ---- fused finalize: apply keep mask to preloaded data ----
    {
        bool k0 = keepsh[r0] != 0, k1 = keepsh[r1] != 0;
        float m0 = k0 ? 1.0f : 0.0f, m1 = k1 ? 1.0f : 0.0f;
        reinterpret_cast<float4*>(out)[g0] =
            make_float4(bx0.x * m0, bx0.y * m0, bx0.z * m0, bx0.w * m0);
        reinterpret_cast<float4*>(out)[g1] =
            make_float4(bx1.x * m1, bx1.y * m1, bx1.z * m1, bx1.w * m1);
        out[BATCH * TOPK * 4 + g0] = k0 ? s0 : 0.0f;
        out[BATCH * TOPK * 4 + g1] = k1 ? s1 : 0.0f;
        out[BATCH * TOPK * 5 + g0] = k0 ? lab0 : 0.0f;
        out[BATCH * TOPK * 5 + g1] = k1 ? lab1 : 0.0f;
    }
}

// ---------------- launch ----------------
extern "C" void kernel_launch(void* const* d_in, const int* in_sizes, int n_in,
                              void* d_out, int out_size) {
    const float* boxes = (const float*)d_in[0];   // [16,25200,4]
    const float* obj   = (const float*)d_in[1];   // [16,25200]
    const float* cls   = (const float*)d_in[2];   // [16,25200,80]
    float* out = (float*)d_out;

    k_scores<<<(BATCH * NA) / 128, 128>>>(obj, cls);
    k_topk<<<BATCH, 1024>>>(boxes);
    dim3 g3(32, 32, BATCH);
    k_mask<<<g3, 64>>>();
    k_reduce_final<<<BATCH, 1024>>>(out);
}